// round 11
// baseline (speedup 1.0000x reference)
#include <cuda_runtime.h>
#include <cuda_fp16.h>

// model_6408091205990: 1.23M independent tiny GRUs (T=10, I=1, H=5) + FC(5->3).
// Round-10: pipe model (validated R3..R9): FFMA2(f32x2, 3 distinct 64b ops) runs
// rt3 from RF banking; fma pipe is the binder at ~177 cyc/step.  r/z gate path
// moved to HFMA2 (rt2, 1 MAC/cyc): f16 weights, f16 matvec, tanh.approx.f16x2
// directly on the f16 preacts (no cvt-in), sigmoid scale in f16, and f16->f32
// return via SHIFT-based bit remap (LOP3/SHF/LEA, ALU pipe only -- no IMAD;
// sigmoids > 0 so f16 sign bits are 0).  n-gate stays f32 (feeds h directly).
// fma/step 177 -> ~154, MUFU 120 -> 80.

#define NB 4096
#define NT 10
#define NS 301
#define NH 5
#define NO 3
#define NSEQ (NB * NS)
#define THREADS 128

typedef unsigned long long ull;

__device__ __forceinline__ ull pack2(float lo, float hi) {
    ull r; asm("mov.b64 %0, {%1, %2};" : "=l"(r) : "f"(lo), "f"(hi)); return r;
}
__device__ __forceinline__ void unpack2(ull v, float& lo, float& hi) {
    asm("mov.b64 {%0, %1}, %2;" : "=f"(lo), "=f"(hi) : "l"(v));
}
__device__ __forceinline__ ull fma2(ull a, ull b, ull c) {
    ull d; asm("fma.rn.f32x2 %0, %1, %2, %3;" : "=l"(d) : "l"(a), "l"(b), "l"(c));
    return d;
}
__device__ __forceinline__ float tanh_mufu(float x) {
    float y; asm("tanh.approx.f32 %0, %1;" : "=f"(y) : "f"(x)); return y;
}
__device__ __forceinline__ unsigned tanh_h2(unsigned x) {
    unsigned y; asm("tanh.approx.f16x2 %0, %1;" : "=r"(y) : "r"(x)); return y;
}
__device__ __forceinline__ unsigned h2u(__half2 h) {
    return *reinterpret_cast<unsigned*>(&h);
}
__device__ __forceinline__ __half2 u2h(unsigned u) {
    return *reinterpret_cast<__half2*>(&u);
}

__global__ __launch_bounds__(THREADS)
void gru_fused_kernel(const float* __restrict__ x,
                      const float* __restrict__ w_ih,
                      const float* __restrict__ w_hh,
                      const float* __restrict__ b_ih,
                      const float* __restrict__ b_hh,
                      const float* __restrict__ fc_w,
                      const float* __restrict__ fc_b,
                      float* __restrict__ out)
{
    const int n = blockIdx.x * THREADS + threadIdx.x;
    if (n >= NSEQ) return;
    const int b = n / NS;
    const int s = n - b * NS;

    // ---- weight prep --------------------------------------------------------
    // r/z path in f16: lanes are (r, z) per output j; 0.5 pre-scale folded in.
    __half2 wrz16_x[NH];      // (0.5*w_ih[r][j], 0.5*w_ih[z][j])
    __half2 brz16[NH];        // 0.5*(b_ih+b_hh) for (r, z)
    __half2 wrz16_h[NH][NH];  // [j][k]
    // n-gate path in f32 (as R3).
    ull wn_h2[2][NH];         // [p][k] = (w_hh[n,2p,k], w_hh[n,2p+1,k])
    float wn_h4[NH];
    ull bn2[2];
    float bn4;
    ull win2[2], bin2[2];
    float win4, bin4;

    #pragma unroll
    for (int j = 0; j < NH; j++) {
        wrz16_x[j] = __floats2half2_rn(0.5f * __ldg(&w_ih[j]),
                                       0.5f * __ldg(&w_ih[NH + j]));
        brz16[j]   = __floats2half2_rn(0.5f * (__ldg(&b_ih[j]) + __ldg(&b_hh[j])),
                                       0.5f * (__ldg(&b_ih[NH + j]) + __ldg(&b_hh[NH + j])));
        #pragma unroll
        for (int k = 0; k < NH; k++)
            wrz16_h[j][k] = __floats2half2_rn(0.5f * __ldg(&w_hh[j * NH + k]),
                                              0.5f * __ldg(&w_hh[(NH + j) * NH + k]));
    }
    #pragma unroll
    for (int p = 0; p < 2; p++) {
        bn2[p]  = pack2(__ldg(&b_hh[2 * NH + 2 * p]), __ldg(&b_hh[2 * NH + 2 * p + 1]));
        win2[p] = pack2(__ldg(&w_ih[2 * NH + 2 * p]), __ldg(&w_ih[2 * NH + 2 * p + 1]));
        bin2[p] = pack2(__ldg(&b_ih[2 * NH + 2 * p]), __ldg(&b_ih[2 * NH + 2 * p + 1]));
        #pragma unroll
        for (int k = 0; k < NH; k++)
            wn_h2[p][k] = pack2(__ldg(&w_hh[(2 * NH + 2 * p) * NH + k]),
                                __ldg(&w_hh[(2 * NH + 2 * p + 1) * NH + k]));
    }
    bn4  = __ldg(&b_hh[2 * NH + 4]);
    win4 = __ldg(&w_ih[2 * NH + 4]);
    bin4 = __ldg(&b_ih[2 * NH + 4]);
    #pragma unroll
    for (int k = 0; k < NH; k++) wn_h4[k] = __ldg(&w_hh[(2 * NH + 4) * NH + k]);

    const ull NEG1_2 = pack2(-1.0f, -1.0f);
    const __half2 H05 = __floats2half2_rn(0.5f, 0.5f);

    // ---- GRU recurrence, fully unrolled -------------------------------------
    float h[NH] = {0.f, 0.f, 0.f, 0.f, 0.f};
    ull h01 = pack2(0.f, 0.f), h23 = h01;
    const float* xp = x + (size_t)b * (NT * NS) + s;

    #pragma unroll
    for (int t = 0; t < NT; t++) {
        const float xv = __ldg(xp + t * NS);
        const ull xv2 = pack2(xv, xv);
        const __half2 x16 = __float2half2_rn(xv);   // 1 F2FP

        // r/z pre-activations in f16 (0.5-scaled), lanes (r, z)
        __half2 arz16[NH];
        #pragma unroll
        for (int j = 0; j < NH; j++) arz16[j] = __hfma2(x16, wrz16_x[j], brz16[j]);

        // n-gate hidden part (f32)
        ull an2[2] = {bn2[0], bn2[1]};
        float ah4 = bn4;

        if (t > 0) {  // h == 0 at t == 0: skip the entire h-matvec
            __half2 h16[NH];
            ull hb[NH];
            #pragma unroll
            for (int k = 0; k < NH; k++) {
                h16[k] = __float2half2_rn(h[k]);    // F2FP broadcast
                hb[k]  = pack2(h[k], h[k]);
            }
            #pragma unroll
            for (int k = 0; k < NH; k++) {
                #pragma unroll
                for (int j = 0; j < NH; j++)
                    arz16[j] = __hfma2(wrz16_h[j][k], h16[k], arz16[j]);
                an2[0] = fma2(wn_h2[0][k], hb[k], an2[0]);
                an2[1] = fma2(wn_h2[1][k], hb[k], an2[1]);
                ah4 = fmaf(wn_h4[k], h[k], ah4);
            }
        }
        float ah[NH];
        unpack2(an2[0], ah[0], ah[1]);
        unpack2(an2[1], ah[2], ah[3]);
        ah[4] = ah4;

        // n-gate x-projection (f32), packed across j pairs
        float ai[NH];
        {
            ull ai01 = fma2(xv2, win2[0], bin2[0]);
            ull ai23 = fma2(xv2, win2[1], bin2[1]);
            unpack2(ai01, ai[0], ai[1]);
            unpack2(ai23, ai[2], ai[3]);
            ai[4] = fmaf(xv, win4, bin4);
        }

        // gates: tanh.f16x2 on (ar,az) directly; sigmoid = 0.5*t + 0.5 in f16;
        // f16->f32 via shift remap (ALU pipe; sigmoid > 0 so sign bits clear):
        //   f32bits = (h16bits << 13) + 0x38000000
        float z[NH], nn[NH];
        #pragma unroll
        for (int j = 0; j < NH; j++) {
            unsigned t2 = tanh_h2(h2u(arz16[j]));
            unsigned s2 = h2u(__hfma2(u2h(t2), H05, H05));
            const float r = __uint_as_float(((s2 & 0xFFFFu) << 13) + 0x38000000u);
            z[j]          = __uint_as_float(((s2 >> 16)     << 13) + 0x38000000u);
            nn[j] = tanh_mufu(fmaf(r, ah[j], ai[j]));
        }

        // h update (1-z)*n + z*h = z*(h-n) + n, j-pair packed (f32)
        {
            ull nn01 = pack2(nn[0], nn[1]);
            ull nn23 = pack2(nn[2], nn[3]);
            ull z01  = pack2(z[0], z[1]);
            ull z23  = pack2(z[2], z[3]);
            h01 = fma2(z01, fma2(nn01, NEG1_2, h01), nn01);
            h23 = fma2(z23, fma2(nn23, NEG1_2, h23), nn23);
            h[4] = fmaf(z[4], h[4] - nn[4], nn[4]);
            unpack2(h01, h[0], h[1]);
            unpack2(h23, h[2], h[3]);
        }
    }

    // ---- FC(5 -> 3), strided write out[b][o][s] -----------------------------
    #pragma unroll
    for (int o = 0; o < NO; o++) {
        float y = __ldg(&fc_b[o]);
        #pragma unroll
        for (int k = 0; k < NH; k++) y = fmaf(__ldg(&fc_w[o * NH + k]), h[k], y);
        out[((size_t)b * NO + o) * NS + s] = y;
    }
}

extern "C" void kernel_launch(void* const* d_in, const int* in_sizes, int n_in,
                              void* d_out, int out_size)
{
    const float* x    = (const float*)d_in[0];
    const float* w_ih = (const float*)d_in[1];
    const float* w_hh = (const float*)d_in[2];
    const float* b_ih = (const float*)d_in[3];
    const float* b_hh = (const float*)d_in[4];
    const float* fc_w = (const float*)d_in[5];
    const float* fc_b = (const float*)d_in[6];
    float* out = (float*)d_out;

    const int grid = (NSEQ + THREADS - 1) / THREADS;
    gru_fused_kernel<<<grid, THREADS>>>(x, w_ih, w_hh, b_ih, b_hh, fc_w, fc_b, out);
}

// round 13
// speedup vs baseline: 1.1716x; 1.1716x over previous
#include <cuda_runtime.h>
#include <cuda_bf16.h>

// model_6408091205990: 1.23M independent tiny GRUs (T=10, I=1, H=5) + FC(5->3).
// Round-11: validated pipe model (fits R1..R10): dur ~= 0.47us x max(MUFU,fma)
// cyc/step; MUFU: tanh.f32=8, tanh.f16x2=16(!), cvt=4 (same pipe).  R3 is at a
// balanced dual floor (MUFU 120 / fma ~128).  This round: exact-f32 trims only:
// all scalar-lane stragglers packed with dummy lanes (n-gate row4, ai, FC pair)
// -> fma ~128 -> ~122 cyc/step, issue count -8/step.  Math identical to R3.

#define NB 4096
#define NT 10
#define NS 301
#define NH 5
#define NO 3
#define NSEQ (NB * NS)
#define THREADS 128

typedef unsigned long long ull;

__device__ __forceinline__ ull pack2(float lo, float hi) {
    ull r; asm("mov.b64 %0, {%1, %2};" : "=l"(r) : "f"(lo), "f"(hi)); return r;
}
__device__ __forceinline__ void unpack2(ull v, float& lo, float& hi) {
    asm("mov.b64 {%0, %1}, %2;" : "=f"(lo), "=f"(hi) : "l"(v));
}
__device__ __forceinline__ ull fma2(ull a, ull b, ull c) {
    ull d; asm("fma.rn.f32x2 %0, %1, %2, %3;" : "=l"(d) : "l"(a), "l"(b), "l"(c));
    return d;
}
__device__ __forceinline__ float tanh_mufu(float x) {
    float y; asm("tanh.approx.f32 %0, %1;" : "=f"(y) : "f"(x)); return y;
}

__global__ __launch_bounds__(THREADS)
void gru_fused_kernel(const float* __restrict__ x,
                      const float* __restrict__ w_ih,
                      const float* __restrict__ w_hh,
                      const float* __restrict__ b_ih,
                      const float* __restrict__ b_hh,
                      const float* __restrict__ fc_w,
                      const float* __restrict__ fc_b,
                      float* __restrict__ out)
{
    const int n = blockIdx.x * THREADS + threadIdx.x;
    if (n >= NSEQ) return;
    const int b = n / NS;
    const int s = n - b * NS;

    // ---- weight prep (uniform broadcast loads; 0.5 folded into r/z rows) ----
    ull wrz_x[NH];        // (0.5*w_ih[r][j], 0.5*w_ih[z][j])
    ull brz2[NH];         // 0.5*(b_ih+b_hh) for (r, z)
    ull wrz_h[NH][NH];    // [j][k] = (0.5*w_hh[r,j,k], 0.5*w_hh[z,j,k])
    // n-gate rows packed (0,1), (2,3), (4, dummy0) -- all lanes fma2.
    ull wn_h2[3][NH];     // [p][k]
    ull bn2[3];
    ull win2[3], bin2[3];

    #pragma unroll
    for (int j = 0; j < NH; j++) {
        wrz_x[j] = pack2(0.5f * __ldg(&w_ih[j]), 0.5f * __ldg(&w_ih[NH + j]));
        brz2[j]  = pack2(0.5f * (__ldg(&b_ih[j]) + __ldg(&b_hh[j])),
                         0.5f * (__ldg(&b_ih[NH + j]) + __ldg(&b_hh[NH + j])));
        #pragma unroll
        for (int k = 0; k < NH; k++)
            wrz_h[j][k] = pack2(0.5f * __ldg(&w_hh[j * NH + k]),
                                0.5f * __ldg(&w_hh[(NH + j) * NH + k]));
    }
    #pragma unroll
    for (int p = 0; p < 3; p++) {
        const int j0 = 2 * p, j1 = 2 * p + 1;          // j1 == 5 -> dummy lane
        const float bhi = (j1 < NH) ? __ldg(&b_hh[2 * NH + j1]) : 0.f;
        const float whi = (j1 < NH) ? __ldg(&w_ih[2 * NH + j1]) : 0.f;
        const float bii = (j1 < NH) ? __ldg(&b_ih[2 * NH + j1]) : 0.f;
        bn2[p]  = pack2(__ldg(&b_hh[2 * NH + j0]), bhi);
        win2[p] = pack2(__ldg(&w_ih[2 * NH + j0]), whi);
        bin2[p] = pack2(__ldg(&b_ih[2 * NH + j0]), bii);
        #pragma unroll
        for (int k = 0; k < NH; k++) {
            const float whh_hi = (j1 < NH) ? __ldg(&w_hh[(2 * NH + j1) * NH + k]) : 0.f;
            wn_h2[p][k] = pack2(__ldg(&w_hh[(2 * NH + j0) * NH + k]), whh_hi);
        }
    }

    const ull NEG1_2 = pack2(-1.0f, -1.0f);
    const ull HALF2  = pack2(0.5f, 0.5f);

    // ---- GRU recurrence, fully unrolled -------------------------------------
    float h[NH] = {0.f, 0.f, 0.f, 0.f, 0.f};
    ull h01 = pack2(0.f, 0.f), h23 = h01;
    const float* xp = x + (size_t)b * (NT * NS) + s;

    #pragma unroll
    for (int t = 0; t < NT; t++) {
        const float xv = __ldg(xp + t * NS);
        const ull xv2 = pack2(xv, xv);

        // r/z pre-activations (0.5-scaled): x part
        ull arz[NH];
        #pragma unroll
        for (int j = 0; j < NH; j++) arz[j] = fma2(xv2, wrz_x[j], brz2[j]);

        // n-gate hidden part (3 packed accumulators, last has dummy hi lane)
        ull an2[3] = {bn2[0], bn2[1], bn2[2]};

        if (t > 0) {  // h == 0 at t == 0: skip the entire h-matvec
            ull hb[NH];
            #pragma unroll
            for (int k = 0; k < NH; k++) hb[k] = pack2(h[k], h[k]);
            #pragma unroll
            for (int k = 0; k < NH; k++) {
                #pragma unroll
                for (int j = 0; j < NH; j++)
                    arz[j] = fma2(wrz_h[j][k], hb[k], arz[j]);
                an2[0] = fma2(wn_h2[0][k], hb[k], an2[0]);
                an2[1] = fma2(wn_h2[1][k], hb[k], an2[1]);
                an2[2] = fma2(wn_h2[2][k], hb[k], an2[2]);
            }
        }
        float ah[NH], dummy;
        unpack2(an2[0], ah[0], ah[1]);
        unpack2(an2[1], ah[2], ah[3]);
        unpack2(an2[2], ah[4], dummy);

        // n-gate x-projection, fully packed (3rd pair has dummy hi lane)
        float ai[NH];
        {
            ull ai01 = fma2(xv2, win2[0], bin2[0]);
            ull ai23 = fma2(xv2, win2[1], bin2[1]);
            ull ai4d = fma2(xv2, win2[2], bin2[2]);
            unpack2(ai01, ai[0], ai[1]);
            unpack2(ai23, ai[2], ai[3]);
            unpack2(ai4d, ai[4], dummy);
        }

        // gate epilogue: sigmoid via 0.5*tanh(0.5x)+0.5, r/z pair-packed
        float z[NH], nn[NH];
        #pragma unroll
        for (int j = 0; j < NH; j++) {
            float ar, az;
            unpack2(arz[j], ar, az);
            ull t2 = pack2(tanh_mufu(ar), tanh_mufu(az));
            ull rz = fma2(HALF2, t2, HALF2);
            float r;
            unpack2(rz, r, z[j]);
            nn[j] = tanh_mufu(fmaf(r, ah[j], ai[j]));
        }

        // h update (1-z)*n + z*h = z*(h-n) + n, j-pair packed
        {
            ull nn01 = pack2(nn[0], nn[1]);
            ull nn23 = pack2(nn[2], nn[3]);
            ull z01  = pack2(z[0], z[1]);
            ull z23  = pack2(z[2], z[3]);
            h01 = fma2(z01, fma2(nn01, NEG1_2, h01), nn01);
            h23 = fma2(z23, fma2(nn23, NEG1_2, h23), nn23);
            h[4] = fmaf(z[4], h[4] - nn[4], nn[4]);
            unpack2(h01, h[0], h[1]);
            unpack2(h23, h[2], h[3]);
        }
    }

    // ---- FC(5 -> 3): outputs (o0,o1) packed, o2 scalar ----------------------
    {
        ull y01 = pack2(__ldg(&fc_b[0]), __ldg(&fc_b[1]));
        float y2 = __ldg(&fc_b[2]);
        #pragma unroll
        for (int k = 0; k < NH; k++) {
            const ull wk = pack2(__ldg(&fc_w[k]), __ldg(&fc_w[NH + k]));
            const ull hk = pack2(h[k], h[k]);
            y01 = fma2(wk, hk, y01);
            y2  = fmaf(__ldg(&fc_w[2 * NH + k]), h[k], y2);
        }
        float y0, y1;
        unpack2(y01, y0, y1);
        out[((size_t)b * NO + 0) * NS + s] = y0;
        out[((size_t)b * NO + 1) * NS + s] = y1;
        out[((size_t)b * NO + 2) * NS + s] = y2;
    }
}

extern "C" void kernel_launch(void* const* d_in, const int* in_sizes, int n_in,
                              void* d_out, int out_size)
{
    const float* x    = (const float*)d_in[0];
    const float* w_ih = (const float*)d_in[1];
    const float* w_hh = (const float*)d_in[2];
    const float* b_ih = (const float*)d_in[3];
    const float* b_hh = (const float*)d_in[4];
    const float* fc_w = (const float*)d_in[5];
    const float* fc_b = (const float*)d_in[6];
    float* out = (float*)d_out;

    const int grid = (NSEQ + THREADS - 1) / THREADS;
    gru_fused_kernel<<<grid, THREADS>>>(x, w_ih, w_hh, b_ih, b_hh, fc_w, fc_b, out);
}